// round 15
// baseline (speedup 1.0000x reference)
#include <cuda_runtime.h>
#include <cuda_bf16.h>
#include <cstdint>

#define NNODES   100000
#define SSAMP    16
#define NODE_DIM 128
#define EDGE_DIM 64
#define EMB_DIM  128
#define KTOT     320            // 128 self + 128 neigh-agg + 64 edge-mean

// ---------------- device-global scratch (no allocs allowed) ------------------
__device__ __align__(16) __nv_bfloat16 g_Nh[(size_t)NNODES * NODE_DIM]; // bf16 gather table
__device__ __align__(16) float         g_A [(size_t)NNODES * NODE_DIM]; // tf32 neigh mean
__device__ __align__(16) float         g_Eb[(size_t)NNODES * EDGE_DIM]; // tf32 edge mean
__device__ __align__(16) float         g_Wt[EMB_DIM * KTOT];            // tf32 W^T [n][k]
__device__ float g_bias[EMB_DIM];

// ---------------- helpers ----------------------------------------------------
__device__ __forceinline__ uint32_t smem_u32(const void* p) {
    uint32_t a;
    asm("{ .reg .u64 t; cvta.to.shared.u64 t, %1; cvt.u32.u64 %0, t; }" : "=r"(a) : "l"(p));
    return a;
}
__device__ __forceinline__ float tf32r(float x) {
    uint32_t u;
    asm("cvt.rna.tf32.f32 %0, %1;" : "=r"(u) : "f"(x));
    return __uint_as_float(u);
}
__device__ __forceinline__ void ldsm_x4(uint32_t* r, uint32_t addr) {
    asm volatile("ldmatrix.sync.aligned.m8n8.x4.shared.b16 {%0,%1,%2,%3}, [%4];"
        : "=r"(r[0]), "=r"(r[1]), "=r"(r[2]), "=r"(r[3]) : "r"(addr));
}
__device__ __forceinline__ void mma1688(float* d, const uint32_t* a, const uint32_t* b) {
    asm volatile("mma.sync.aligned.m16n8k8.row.col.f32.tf32.tf32.f32 "
        "{%0,%1,%2,%3}, {%4,%5,%6,%7}, {%8,%9}, {%0,%1,%2,%3};"
        : "+f"(d[0]), "+f"(d[1]), "+f"(d[2]), "+f"(d[3])
        : "r"(a[0]), "r"(a[1]), "r"(a[2]), "r"(a[3]), "r"(b[0]), "r"(b[1]));
}
__device__ __forceinline__ void cpa16(uint32_t dst, const void* src) {
    asm volatile("cp.async.cg.shared.global [%0], [%1], 16;" :: "r"(dst), "l"(src));
}
#define CP_COMMIT() asm volatile("cp.async.commit_group;" ::: "memory")
#define CP_WAIT1()  asm volatile("cp.async.wait_group 1;" ::: "memory")
#define CP_WAIT0()  asm volatile("cp.async.wait_group 0;" ::: "memory")

// ===========================================================================
// K0 "prep": modulo-interleaved roles so edge-mean (DRAM stream) and
//   bf16-table convert (latency-bound) are co-resident in every wave.
//   bid % 9 == 8 -> convert block (bid/9 in 0..1562)
//   else         -> edge block    (bid - bid/9, guarded < 12500)
//   bid >= MIXB  -> weight fold (41 blocks)
// ===========================================================================
#define NTOT  ((size_t)NNODES * NODE_DIM)       // 12.8M floats
#define CONVB 1563
#define EDGEB 12500
#define MIXB  14067                             // conv ids 0..1562 at bid=9c+8
#define FOLDB 41

__global__ __launch_bounds__(256) void prep(
        const float* __restrict__ node_feat,
        const float* __restrict__ edge_feat,
        const float* __restrict__ W_edge, const float* __restrict__ b_edge,
        const float* __restrict__ W_lin,  const float* __restrict__ b_lin) {
    const int tid = threadIdx.x;
    const int bid = blockIdx.x;

    if (bid < MIXB) {
        if ((bid % 9) == 8) {
            // -------- convert role: bf16 gather table, coalesced MLP=8 --------
            int cb = bid / 9;                       // 0..1562
            size_t base = (size_t)cb * 8192 + (size_t)tid * 4;
            float4 v[8];
            #pragma unroll
            for (int i = 0; i < 8; i++) {
                size_t idx = base + (size_t)i * 1024;
                v[i] = (idx < NTOT) ? *(const float4*)(node_feat + idx)
                                    : make_float4(0.f, 0.f, 0.f, 0.f);
            }
            #pragma unroll
            for (int i = 0; i < 8; i++) {
                size_t idx = base + (size_t)i * 1024;
                if (idx < NTOT) {
                    __nv_bfloat162 h01 = __floats2bfloat162_rn(v[i].x, v[i].y);
                    __nv_bfloat162 h23 = __floats2bfloat162_rn(v[i].z, v[i].w);
                    *(uint2*)(g_Nh + idx) = make_uint2(*(uint32_t*)&h01, *(uint32_t*)&h23);
                }
            }
            return;
        }
        // -------- edge role: warp-per-node edge mean -> g_Eb --------
        int eb = bid - bid / 9;                     // 0..12503
        if (eb >= EDGEB) return;
        int node = (int)(((size_t)eb * 256 + tid) >> 5);
        if (node >= NNODES) return;
        int lane = tid & 31;
        const float* ep = edge_feat + (size_t)node * (SSAMP * EDGE_DIM);
        int halfrow = lane >> 4, cg = lane & 15;
        float4 ea = make_float4(0.f, 0.f, 0.f, 0.f);
        #pragma unroll
        for (int r = 0; r < SSAMP; r += 2) {
            float4 v = *(const float4*)(ep + (size_t)(r + halfrow) * EDGE_DIM + cg * 4);
            ea.x += v.x; ea.y += v.y; ea.z += v.z; ea.w += v.w;
        }
        ea.x += __shfl_xor_sync(0xffffffffu, ea.x, 16);
        ea.y += __shfl_xor_sync(0xffffffffu, ea.y, 16);
        ea.z += __shfl_xor_sync(0xffffffffu, ea.z, 16);
        ea.w += __shfl_xor_sync(0xffffffffu, ea.w, 16);
        if (lane < 16) {
            const float inv = 1.0f / (float)SSAMP;
            float4 oe;
            oe.x = tf32r(ea.x * inv); oe.y = tf32r(ea.y * inv);
            oe.z = tf32r(ea.z * inv); oe.w = tf32r(ea.w * inv);
            *(float4*)(g_Eb + (size_t)node * EDGE_DIM + cg * 4) = oe;
        }
        return;
    }

    // -------- weight fold --------
    int kid = bid - MIXB;                  // 0..40
    if (kid == 40) {
        int j = tid;
        if (j < EMB_DIM) {
            float acc = b_lin[j];
            for (int c = 0; c < NODE_DIM; c++)
                acc += b_edge[c] * W_lin[(NODE_DIM + c) * EMB_DIM + j];
            g_bias[j] = acc;
        }
        return;
    }
    int kk = tid >> 7;
    int j  = tid & 127;
    #pragma unroll
    for (int r = 0; r < 4; r++) {
        int k = kid * 8 + r * 2 + kk;      // 0..319
        float w;
        if (k < 2 * NODE_DIM) {
            w = W_lin[k * EMB_DIM + j];
        } else {
            int e = k - 2 * NODE_DIM;
            float acc = 0.f;
            #pragma unroll 4
            for (int c = 0; c < NODE_DIM; c++)
                acc += W_edge[e * NODE_DIM + c] * W_lin[(NODE_DIM + c) * EMB_DIM + j];
            w = acc;
        }
        g_Wt[j * KTOT + k] = tf32r(w);
    }
}

// ===========================================================================
// K1: gather-only (warp per node): mean of 16 bf16 rows -> g_A (tf32 fp32)
// ===========================================================================
__global__ __launch_bounds__(256) void gather_agg(const int* __restrict__ src_idx) {
    int node = (int)((blockIdx.x * blockDim.x + threadIdx.x) >> 5);
    if (node >= NNODES) return;
    int lane = threadIdx.x & 31;

    int s = 0;
    if (lane < SSAMP) s = src_idx[(size_t)node * SSAMP + lane];
    float4 na = make_float4(0.f, 0.f, 0.f, 0.f);
    #pragma unroll
    for (int r = 0; r < SSAMP; r++) {
        int sr = __shfl_sync(0xffffffffu, s, r);
        uint2 pv = *(const uint2*)(g_Nh + (size_t)sr * NODE_DIM + lane * 4);
        float2 f0 = __bfloat1622float2(*(const __nv_bfloat162*)&pv.x);
        float2 f1 = __bfloat1622float2(*(const __nv_bfloat162*)&pv.y);
        na.x += f0.x; na.y += f0.y; na.z += f1.x; na.w += f1.y;
    }
    const float inv = 1.0f / (float)SSAMP;
    float4 oa;
    oa.x = tf32r(na.x * inv); oa.y = tf32r(na.y * inv);
    oa.z = tf32r(na.z * inv); oa.w = tf32r(na.w * inv);
    *(float4*)(g_A + (size_t)node * NODE_DIM + lane * 4) = oa;
}

// ===========================================================================
// K2: single-product tf32 GEMM (m16n8k8), XOR-swizzled 128B smem rows,
//     3-stage cp.async ring. Self columns staged straight from node_feat.
// ===========================================================================
#define TILEB    16384                    // 128 rows x 128B, per A / B
#define STAGE    (2 * TILEB)              // 32KB
#define NSTAGE   3
#define SM_TOTAL (NSTAGE * STAGE)         // 98304

__global__ __launch_bounds__(256, 2) void gemm_tf32(const float* __restrict__ node_feat,
                                                    float* __restrict__ out) {
    extern __shared__ unsigned char smem[];
    const int tid  = threadIdx.x;
    const int lane = tid & 31;
    const int wid  = tid >> 5;
    const int m0   = blockIdx.x * 128;

    const int mw = (wid & 3) * 32;
    const int nw = (wid >> 2) * 64;
    const uint32_t sb = smem_u32(smem);

    int er[4], eu[4], mr[4];
    uint32_t dsto[4];
    #pragma unroll
    for (int p = 0; p < 4; p++) {
        int e = tid + p * 256;
        er[p] = e >> 3;
        eu[p] = e & 7;
        int m = m0 + er[p]; if (m >= NNODES) m = NNODES - 1;
        mr[p] = m;
        dsto[p] = (uint32_t)(er[p] * 128 + ((eu[p] ^ (er[p] & 7)) << 4));
    }

    const int row_a = mw + (lane & 7) + (lane & 8);
    const int keyA  = row_a & 7;
    const int selA  = lane >> 4;
    const int row_b = nw + (lane & 7) + ((lane >> 4) << 3);
    const int keyB  = row_b & 7;
    const int selB  = (lane >> 3) & 1;

    float C[2][8][4];
    #pragma unroll
    for (int a = 0; a < 2; a++)
        #pragma unroll
        for (int j = 0; j < 8; j++)
            #pragma unroll
            for (int q = 0; q < 4; q++) C[a][j][q] = 0.f;

    auto stage_chunk = [&](int ch, uint32_t st) {
        const char* as; size_t astr;
        if (ch < 4)      { as = (const char*)node_feat + ch * 128;  astr = 512; }
        else if (ch < 8) { as = (const char*)g_A  + (ch - 4) * 128; astr = 512; }
        else             { as = (const char*)g_Eb + (ch - 8) * 128; astr = 256; }
        const char* bs = (const char*)g_Wt + ch * 128;
        #pragma unroll
        for (int p = 0; p < 4; p++)
            cpa16(st + dsto[p], as + (size_t)mr[p] * astr + eu[p] * 16);
        #pragma unroll
        for (int p = 0; p < 4; p++)
            cpa16(st + TILEB + dsto[p], bs + (size_t)er[p] * 1280 + eu[p] * 16);
        CP_COMMIT();
    };

    stage_chunk(0, sb);
    stage_chunk(1, sb + STAGE);

    int slot = 0, nslot = 2;
    #pragma unroll 1
    for (int ch = 0; ch < 10; ch++) {
        if (ch < 9) { CP_WAIT1(); } else { CP_WAIT0(); }
        __syncthreads();
        if (ch < 8) stage_chunk(ch + 2, sb + nslot * STAGE);

        const uint32_t aBase = sb + slot * STAGE + (uint32_t)(row_a * 128);
        const uint32_t bBase = sb + slot * STAGE + TILEB + (uint32_t)(row_b * 128);

        #pragma unroll
        for (int k = 0; k < 4; k++) {
            const uint32_t ua = (uint32_t)(((2 * k + selA) ^ keyA) << 4);
            const uint32_t ub = (uint32_t)(((2 * k + selB) ^ keyB) << 4);
            uint32_t a[2][4], bb[16];

            ldsm_x4(a[0], aBase + ua);
            ldsm_x4(a[1], aBase + 2048 + ua);
            ldsm_x4(&bb[0],  bBase + ub);
            ldsm_x4(&bb[4],  bBase + 2048 + ub);
            ldsm_x4(&bb[8],  bBase + 4096 + ub);
            ldsm_x4(&bb[12], bBase + 6144 + ub);

            #pragma unroll
            for (int mh = 0; mh < 2; mh++)
                #pragma unroll
                for (int j = 0; j < 8; j++)
                    mma1688(C[mh][j], a[mh], &bb[j * 2]);
        }
        slot  = (slot == 2) ? 0 : slot + 1;
        nslot = (nslot == 2) ? 0 : nslot + 1;
    }

    #pragma unroll
    for (int a = 0; a < 2; a++) {
        int row = m0 + mw + a * 16 + (lane >> 2);
        #pragma unroll
        for (int j = 0; j < 8; j++) {
            int col = nw + j * 8 + 2 * (lane & 3);
            float bx = g_bias[col], by = g_bias[col + 1];
            if (row < NNODES) {
                float2 o;
                o.x = fmaxf(C[a][j][0] + bx, 0.f);
                o.y = fmaxf(C[a][j][1] + by, 0.f);
                *(float2*)(out + (size_t)row * EMB_DIM + col) = o;
            }
            if (row + 8 < NNODES) {
                float2 o;
                o.x = fmaxf(C[a][j][2] + bx, 0.f);
                o.y = fmaxf(C[a][j][3] + by, 0.f);
                *(float2*)(out + (size_t)(row + 8) * EMB_DIM + col) = o;
            }
        }
    }
}

// ===========================================================================
// inputs: node_feat, edge_feat, src_idx, W_edge, b_edge, W_lin, b_lin
// ===========================================================================
extern "C" void kernel_launch(void* const* d_in, const int* in_sizes, int n_in,
                              void* d_out, int out_size) {
    const float* node_feat = (const float*)d_in[0];
    const float* edge_feat = (const float*)d_in[1];
    const int*   src_idx   = (const int*)  d_in[2];
    const float* W_edge    = (const float*)d_in[3];
    const float* b_edge    = (const float*)d_in[4];
    const float* W_lin     = (const float*)d_in[5];
    const float* b_lin     = (const float*)d_in[6];
    float*       out       = (float*)d_out;
    (void)in_sizes; (void)n_in; (void)out_size;

    static int once = 0;
    if (!once) {
        cudaFuncSetAttribute(gemm_tf32, cudaFuncAttributeMaxDynamicSharedMemorySize, SM_TOTAL);
        once = 1;
    }

    prep<<<MIXB + FOLDB, 256>>>(node_feat, edge_feat, W_edge, b_edge, W_lin, b_lin);
    gather_agg<<<12500, 256>>>(src_idx);
    gemm_tf32<<<(NNODES + 127) / 128, 256, SM_TOTAL>>>(node_feat, out);
}

// round 16
// speedup vs baseline: 1.2342x; 1.2342x over previous
#include <cuda_runtime.h>
#include <cuda_bf16.h>
#include <cstdint>

#define NNODES   100000
#define SSAMP    16
#define NODE_DIM 128
#define EDGE_DIM 64
#define EMB_DIM  128
#define KTOT     320            // 128 self + 128 neigh-agg + 64 edge-mean

// ---------------- device-global scratch (no allocs allowed) ------------------
__device__ __align__(16) __nv_bfloat16 g_Nh[(size_t)NNODES * NODE_DIM]; // bf16 gather table
__device__ __align__(16) float         g_A [(size_t)NNODES * NODE_DIM]; // tf32 neigh mean
__device__ __align__(16) float         g_Eb[(size_t)NNODES * EDGE_DIM]; // tf32 edge mean
__device__ __align__(16) float         g_Wt[EMB_DIM * KTOT];            // tf32 W^T [n][k]
__device__ float g_bias[EMB_DIM];

// ---------------- helpers ----------------------------------------------------
__device__ __forceinline__ uint32_t smem_u32(const void* p) {
    uint32_t a;
    asm("{ .reg .u64 t; cvta.to.shared.u64 t, %1; cvt.u32.u64 %0, t; }" : "=r"(a) : "l"(p));
    return a;
}
__device__ __forceinline__ float tf32r(float x) {
    uint32_t u;
    asm("cvt.rna.tf32.f32 %0, %1;" : "=r"(u) : "f"(x));
    return __uint_as_float(u);
}
__device__ __forceinline__ void ldsm_x4(uint32_t* r, uint32_t addr) {
    asm volatile("ldmatrix.sync.aligned.m8n8.x4.shared.b16 {%0,%1,%2,%3}, [%4];"
        : "=r"(r[0]), "=r"(r[1]), "=r"(r[2]), "=r"(r[3]) : "r"(addr));
}
__device__ __forceinline__ void mma1688(float* d, const uint32_t* a, const uint32_t* b) {
    asm volatile("mma.sync.aligned.m16n8k8.row.col.f32.tf32.tf32.f32 "
        "{%0,%1,%2,%3}, {%4,%5,%6,%7}, {%8,%9}, {%0,%1,%2,%3};"
        : "+f"(d[0]), "+f"(d[1]), "+f"(d[2]), "+f"(d[3])
        : "r"(a[0]), "r"(a[1]), "r"(a[2]), "r"(a[3]), "r"(b[0]), "r"(b[1]));
}
__device__ __forceinline__ void cpa16(uint32_t dst, const void* src) {
    asm volatile("cp.async.cg.shared.global [%0], [%1], 16;" :: "r"(dst), "l"(src));
}
#define CP_COMMIT() asm volatile("cp.async.commit_group;" ::: "memory")
#define CP_WAIT1()  asm volatile("cp.async.wait_group 1;" ::: "memory")
#define CP_WAIT0()  asm volatile("cp.async.wait_group 0;" ::: "memory")

// ===========================================================================
// K0: PURE bf16 gather-table conversion (coalesced, MLP=8). Nothing else.
// ===========================================================================
#define NTOT  ((size_t)NNODES * NODE_DIM)       // 12.8M floats
#define CONVB 1563

__global__ __launch_bounds__(256) void convert_tbl(const float* __restrict__ node_feat) {
    const int tid = threadIdx.x;
    size_t base = (size_t)blockIdx.x * 8192 + (size_t)tid * 4;
    float4 v[8];
    #pragma unroll
    for (int i = 0; i < 8; i++) {
        size_t idx = base + (size_t)i * 1024;
        v[i] = (idx < NTOT) ? *(const float4*)(node_feat + idx)
                            : make_float4(0.f, 0.f, 0.f, 0.f);
    }
    #pragma unroll
    for (int i = 0; i < 8; i++) {
        size_t idx = base + (size_t)i * 1024;
        if (idx < NTOT) {
            __nv_bfloat162 h01 = __floats2bfloat162_rn(v[i].x, v[i].y);
            __nv_bfloat162 h23 = __floats2bfloat162_rn(v[i].z, v[i].w);
            *(uint2*)(g_Nh + idx) = make_uint2(*(uint32_t*)&h01, *(uint32_t*)&h23);
        }
    }
}

// ===========================================================================
// K1: fold (blocks 0..40, latency-bound, hides inside the big wave)
//     + combined edge-mean (DRAM) + bf16 gather-mean (L2), warp per node.
// ===========================================================================
#define FOLDB 41
#define AGGB  12500

__global__ __launch_bounds__(256) void aggregate(
        const float* __restrict__ edge_feat,
        const int*   __restrict__ src_idx,
        const float* __restrict__ W_edge, const float* __restrict__ b_edge,
        const float* __restrict__ W_lin,  const float* __restrict__ b_lin) {
    const int tid = threadIdx.x;
    if (blockIdx.x < FOLDB) {
        // ---------------- weight fold (runs first, hides under agg wave) -----
        int kid = blockIdx.x;                  // 0..40
        if (kid == 40) {
            int j = tid;
            if (j < EMB_DIM) {
                float acc = b_lin[j];
                for (int c = 0; c < NODE_DIM; c++)
                    acc += b_edge[c] * W_lin[(NODE_DIM + c) * EMB_DIM + j];
                g_bias[j] = acc;
            }
            return;
        }
        int kk = tid >> 7;
        int j  = tid & 127;
        #pragma unroll
        for (int r = 0; r < 4; r++) {
            int k = kid * 8 + r * 2 + kk;      // 0..319
            float w;
            if (k < 2 * NODE_DIM) {
                w = W_lin[k * EMB_DIM + j];
            } else {
                int e = k - 2 * NODE_DIM;
                float acc = 0.f;
                #pragma unroll 8
                for (int c = 0; c < NODE_DIM; c++)
                    acc += W_edge[e * NODE_DIM + c] * W_lin[(NODE_DIM + c) * EMB_DIM + j];
                w = acc;
            }
            g_Wt[j * KTOT + k] = tf32r(w);
        }
        return;
    }

    // ---------------- per-node edge-mean + gather-mean ----------------
    int node = (int)(((size_t)(blockIdx.x - FOLDB) * 256 + tid) >> 5);
    if (node >= NNODES) return;
    int lane = tid & 31;

    // edge mean (lanes split even/odd rows; DRAM stream)
    const float* ep = edge_feat + (size_t)node * (SSAMP * EDGE_DIM);
    int halfrow = lane >> 4, cg = lane & 15;
    float4 ea = make_float4(0.f, 0.f, 0.f, 0.f);
    #pragma unroll
    for (int r = 0; r < SSAMP; r += 2) {
        float4 v = *(const float4*)(ep + (size_t)(r + halfrow) * EDGE_DIM + cg * 4);
        ea.x += v.x; ea.y += v.y; ea.z += v.z; ea.w += v.w;
    }

    // neighbor gather mean from bf16 table (256B rows, L2)
    int s = 0;
    if (lane < SSAMP) s = src_idx[(size_t)node * SSAMP + lane];
    float4 na = make_float4(0.f, 0.f, 0.f, 0.f);
    #pragma unroll
    for (int r = 0; r < SSAMP; r++) {
        int sr = __shfl_sync(0xffffffffu, s, r);
        uint2 pv = *(const uint2*)(g_Nh + (size_t)sr * NODE_DIM + lane * 4);
        float2 f0 = __bfloat1622float2(*(const __nv_bfloat162*)&pv.x);
        float2 f1 = __bfloat1622float2(*(const __nv_bfloat162*)&pv.y);
        na.x += f0.x; na.y += f0.y; na.z += f1.x; na.w += f1.y;
    }

    ea.x += __shfl_xor_sync(0xffffffffu, ea.x, 16);
    ea.y += __shfl_xor_sync(0xffffffffu, ea.y, 16);
    ea.z += __shfl_xor_sync(0xffffffffu, ea.z, 16);
    ea.w += __shfl_xor_sync(0xffffffffu, ea.w, 16);

    const float inv = 1.0f / (float)SSAMP;
    float4 oa;
    oa.x = tf32r(na.x * inv); oa.y = tf32r(na.y * inv);
    oa.z = tf32r(na.z * inv); oa.w = tf32r(na.w * inv);
    *(float4*)(g_A + (size_t)node * NODE_DIM + lane * 4) = oa;
    if (lane < 16) {
        float4 oe;
        oe.x = tf32r(ea.x * inv); oe.y = tf32r(ea.y * inv);
        oe.z = tf32r(ea.z * inv); oe.w = tf32r(ea.w * inv);
        *(float4*)(g_Eb + (size_t)node * EDGE_DIM + cg * 4) = oe;
    }
}

// ===========================================================================
// K2: single-product tf32 GEMM (m16n8k8), XOR-swizzled 128B smem rows,
//     3-stage cp.async ring. Self columns staged straight from node_feat.
// ===========================================================================
#define TILEB    16384                    // 128 rows x 128B, per A / B
#define STAGE    (2 * TILEB)              // 32KB
#define NSTAGE   3
#define SM_TOTAL (NSTAGE * STAGE)         // 98304

__global__ __launch_bounds__(256, 2) void gemm_tf32(const float* __restrict__ node_feat,
                                                    float* __restrict__ out) {
    extern __shared__ unsigned char smem[];
    const int tid  = threadIdx.x;
    const int lane = tid & 31;
    const int wid  = tid >> 5;
    const int m0   = blockIdx.x * 128;

    const int mw = (wid & 3) * 32;
    const int nw = (wid >> 2) * 64;
    const uint32_t sb = smem_u32(smem);

    int er[4], eu[4], mr[4];
    uint32_t dsto[4];
    #pragma unroll
    for (int p = 0; p < 4; p++) {
        int e = tid + p * 256;
        er[p] = e >> 3;
        eu[p] = e & 7;
        int m = m0 + er[p]; if (m >= NNODES) m = NNODES - 1;
        mr[p] = m;
        dsto[p] = (uint32_t)(er[p] * 128 + ((eu[p] ^ (er[p] & 7)) << 4));
    }

    const int row_a = mw + (lane & 7) + (lane & 8);
    const int keyA  = row_a & 7;
    const int selA  = lane >> 4;
    const int row_b = nw + (lane & 7) + ((lane >> 4) << 3);
    const int keyB  = row_b & 7;
    const int selB  = (lane >> 3) & 1;

    float C[2][8][4];
    #pragma unroll
    for (int a = 0; a < 2; a++)
        #pragma unroll
        for (int j = 0; j < 8; j++)
            #pragma unroll
            for (int q = 0; q < 4; q++) C[a][j][q] = 0.f;

    auto stage_chunk = [&](int ch, uint32_t st) {
        const char* as; size_t astr;
        if (ch < 4)      { as = (const char*)node_feat + ch * 128;  astr = 512; }
        else if (ch < 8) { as = (const char*)g_A  + (ch - 4) * 128; astr = 512; }
        else             { as = (const char*)g_Eb + (ch - 8) * 128; astr = 256; }
        const char* bs = (const char*)g_Wt + ch * 128;
        #pragma unroll
        for (int p = 0; p < 4; p++)
            cpa16(st + dsto[p], as + (size_t)mr[p] * astr + eu[p] * 16);
        #pragma unroll
        for (int p = 0; p < 4; p++)
            cpa16(st + TILEB + dsto[p], bs + (size_t)er[p] * 1280 + eu[p] * 16);
        CP_COMMIT();
    };

    stage_chunk(0, sb);
    stage_chunk(1, sb + STAGE);

    int slot = 0, nslot = 2;
    #pragma unroll 1
    for (int ch = 0; ch < 10; ch++) {
        if (ch < 9) { CP_WAIT1(); } else { CP_WAIT0(); }
        __syncthreads();
        if (ch < 8) stage_chunk(ch + 2, sb + nslot * STAGE);

        const uint32_t aBase = sb + slot * STAGE + (uint32_t)(row_a * 128);
        const uint32_t bBase = sb + slot * STAGE + TILEB + (uint32_t)(row_b * 128);

        #pragma unroll
        for (int k = 0; k < 4; k++) {
            const uint32_t ua = (uint32_t)(((2 * k + selA) ^ keyA) << 4);
            const uint32_t ub = (uint32_t)(((2 * k + selB) ^ keyB) << 4);
            uint32_t a[2][4], bb[16];

            ldsm_x4(a[0], aBase + ua);
            ldsm_x4(a[1], aBase + 2048 + ua);
            ldsm_x4(&bb[0],  bBase + ub);
            ldsm_x4(&bb[4],  bBase + 2048 + ub);
            ldsm_x4(&bb[8],  bBase + 4096 + ub);
            ldsm_x4(&bb[12], bBase + 6144 + ub);

            #pragma unroll
            for (int mh = 0; mh < 2; mh++)
                #pragma unroll
                for (int j = 0; j < 8; j++)
                    mma1688(C[mh][j], a[mh], &bb[j * 2]);
        }
        slot  = (slot == 2) ? 0 : slot + 1;
        nslot = (nslot == 2) ? 0 : nslot + 1;
    }

    #pragma unroll
    for (int a = 0; a < 2; a++) {
        int row = m0 + mw + a * 16 + (lane >> 2);
        #pragma unroll
        for (int j = 0; j < 8; j++) {
            int col = nw + j * 8 + 2 * (lane & 3);
            float bx = g_bias[col], by = g_bias[col + 1];
            if (row < NNODES) {
                float2 o;
                o.x = fmaxf(C[a][j][0] + bx, 0.f);
                o.y = fmaxf(C[a][j][1] + by, 0.f);
                *(float2*)(out + (size_t)row * EMB_DIM + col) = o;
            }
            if (row + 8 < NNODES) {
                float2 o;
                o.x = fmaxf(C[a][j][2] + bx, 0.f);
                o.y = fmaxf(C[a][j][3] + by, 0.f);
                *(float2*)(out + (size_t)(row + 8) * EMB_DIM + col) = o;
            }
        }
    }
}

// ===========================================================================
// inputs: node_feat, edge_feat, src_idx, W_edge, b_edge, W_lin, b_lin
// ===========================================================================
extern "C" void kernel_launch(void* const* d_in, const int* in_sizes, int n_in,
                              void* d_out, int out_size) {
    const float* node_feat = (const float*)d_in[0];
    const float* edge_feat = (const float*)d_in[1];
    const int*   src_idx   = (const int*)  d_in[2];
    const float* W_edge    = (const float*)d_in[3];
    const float* b_edge    = (const float*)d_in[4];
    const float* W_lin     = (const float*)d_in[5];
    const float* b_lin     = (const float*)d_in[6];
    float*       out       = (float*)d_out;
    (void)in_sizes; (void)n_in; (void)out_size;

    static int once = 0;
    if (!once) {
        cudaFuncSetAttribute(gemm_tf32, cudaFuncAttributeMaxDynamicSharedMemorySize, SM_TOTAL);
        once = 1;
    }

    convert_tbl<<<CONVB, 256>>>(node_feat);
    aggregate<<<FOLDB + AGGB, 256>>>(edge_feat, src_idx, W_edge, b_edge, W_lin, b_lin);
    gemm_tf32<<<(NNODES + 127) / 128, 256, SM_TOTAL>>>(node_feat, out);
}